// round 1
// baseline (speedup 1.0000x reference)
#include <cuda_runtime.h>
#include <cstdint>
#include <cstddef>

// Problem dims
#define T_STEPS 512
#define BATCH   256
#define DIM     512
#define HID     256
#define FOURH   1024
#define NACT    32
#define OUTC    33

// Scratch for x_proj: [T, B, 4H] fp32 = 536 MB (device global, no runtime alloc)
__device__ float g_xproj[(size_t)T_STEPS * BATCH * FOURH];

// ---------------------------------------------------------------------------
// Kernel 1: x_proj = inputs @ Wx + b   ([T*B, 512] @ [512, 1024])
// Classic SMEM-tiled fp32 SGEMM, 128x128 tile, BK=16, 256 threads, 8x8/thread
// ---------------------------------------------------------------------------
#define BM 128
#define BN 128
#define BKT 16

__global__ __launch_bounds__(256) void xproj_kernel(
    const float* __restrict__ A,      // [M, 512]
    const float* __restrict__ W,      // [512, 1024]
    const float* __restrict__ bias)   // [1024]
{
    __shared__ float As[BKT][BM];
    __shared__ float Bs[BKT][BN];

    const int tid  = threadIdx.x;
    const int cRow = blockIdx.y;      // M / 128 = 1024 blocks
    const int cCol = blockIdx.x;      // 1024 / 128 = 8 blocks

    // A-tile loader: 128x16 floats = 512 float4; 2 per thread
    const int aRow  = tid >> 2;       // 0..63
    const int aCol4 = tid & 3;        // 0..3
    // B-tile loader: 16x128 floats = 512 float4; 2 per thread
    const int bRow  = tid >> 5;       // 0..7
    const int bCol4 = tid & 31;       // 0..31

    const int ty = tid >> 4;          // 0..15
    const int tx = tid & 15;          // 0..15

    const float* Ab = A + (size_t)cRow * BM * DIM;
    const float* Wb = W + (size_t)cCol * BN;

    float acc[8][8];
    #pragma unroll
    for (int i = 0; i < 8; i++)
        #pragma unroll
        for (int j = 0; j < 8; j++) acc[i][j] = 0.f;

    for (int k0 = 0; k0 < DIM; k0 += BKT) {
        #pragma unroll
        for (int r = 0; r < 2; r++) {
            int row = aRow + 64 * r;
            float4 v = *(const float4*)(Ab + (size_t)row * DIM + k0 + aCol4 * 4);
            As[aCol4 * 4 + 0][row] = v.x;
            As[aCol4 * 4 + 1][row] = v.y;
            As[aCol4 * 4 + 2][row] = v.z;
            As[aCol4 * 4 + 3][row] = v.w;
        }
        #pragma unroll
        for (int r = 0; r < 2; r++) {
            int row = bRow + 8 * r;
            *(float4*)&Bs[row][bCol4 * 4] =
                *(const float4*)(Wb + (size_t)(k0 + row) * FOURH + bCol4 * 4);
        }
        __syncthreads();

        #pragma unroll
        for (int kk = 0; kk < BKT; kk++) {
            float4 m0 = *(const float4*)&As[kk][ty * 8];
            float4 m1 = *(const float4*)&As[kk][ty * 8 + 4];
            float4 n0 = *(const float4*)&Bs[kk][tx * 8];
            float4 n1 = *(const float4*)&Bs[kk][tx * 8 + 4];
            float rm[8] = {m0.x, m0.y, m0.z, m0.w, m1.x, m1.y, m1.z, m1.w};
            float rn[8] = {n0.x, n0.y, n0.z, n0.w, n1.x, n1.y, n1.z, n1.w};
            #pragma unroll
            for (int i = 0; i < 8; i++)
                #pragma unroll
                for (int j = 0; j < 8; j++)
                    acc[i][j] = fmaf(rm[i], rn[j], acc[i][j]);
        }
        __syncthreads();
    }

    // Epilogue: add bias, write to g_xproj
    #pragma unroll
    for (int i = 0; i < 8; i++) {
        size_t row = (size_t)cRow * BM + ty * 8 + i;
        float* Crow = g_xproj + row * FOURH + (size_t)cCol * BN + tx * 8;
        #pragma unroll
        for (int j = 0; j < 8; j += 4) {
            float4 bv = *(const float4*)(bias + cCol * BN + tx * 8 + j);
            float4 o;
            o.x = acc[i][j + 0] + bv.x;
            o.y = acc[i][j + 1] + bv.y;
            o.z = acc[i][j + 2] + bv.z;
            o.w = acc[i][j + 3] + bv.w;
            *(float4*)(Crow + j) = o;
        }
    }
}

// ---------------------------------------------------------------------------
// Kernel 2: persistent recurrent kernel.
// 16 clusters x 8 CTAs. Each cluster owns 16 batch rows for all 512 steps.
// Wh split by columns across the 8 CTAs (gate-aligned: CTA r owns hidden
// units [32r, 32r+32) across all 4 gates => 128 local columns, 128 KB SMEM).
// new_h slice broadcast to peers via DSMEM stores + 1 cluster barrier / step.
// ---------------------------------------------------------------------------
#define CLUSTER 8
#define NB      16      // batch rows per cluster
#define LC      128     // local Wh columns per CTA
#define RTHREADS 256

// SMEM layout (floats):
//  Wh_s   : 256*128 = 32768
//  hbuf   : 2*16*256 = 8192   (ping-pong full-h copies)
//  z_s    : 16*128  = 2048
//  c_s    : 16*32   = 512
//  Wo_s   : 5*256   = 1280
//  bo_s   : 8
#define SM_WH  0
#define SM_HB  32768
#define SM_Z   (SM_HB + 8192)
#define SM_C   (SM_Z + 2048)
#define SM_WO  (SM_C + 512)
#define SM_BO  (SM_WO + 1280)
#define SM_FLOATS (SM_BO + 8)
#define RSMEM_BYTES (SM_FLOATS * 4)

__device__ __forceinline__ uint32_t smem_u32(const void* p) {
    uint32_t a;
    asm("{ .reg .u64 t; cvta.to.shared.u64 t, %1; cvt.u32.u64 %0, t; }"
        : "=r"(a) : "l"(p));
    return a;
}

__device__ __forceinline__ void st_cluster_f32(uint32_t saddr, int rank, float v) {
    asm volatile(
        "{ .reg .b32 ra; mapa.shared::cluster.u32 ra, %0, %1;"
        "  st.shared::cluster.f32 [ra], %2; }"
        :: "r"(saddr), "r"(rank), "f"(v) : "memory");
}

__device__ __forceinline__ float sigf(float x) {
    return 1.f / (1.f + __expf(-x));
}
__device__ __forceinline__ float tanh_f(float x) {
    float e = __expf(-2.f * fabsf(x));   // in (0,1], no overflow
    float t = (1.f - e) / (1.f + e);
    return copysignf(t, x);
}

__global__ void __cluster_dims__(CLUSTER, 1, 1) __launch_bounds__(RTHREADS, 1)
lstm_rec_kernel(const int*   __restrict__ epi,      // [T,B] int32
                const float* __restrict__ carry_c,  // [B,256]
                const float* __restrict__ carry_h,  // [B,256]
                const float* __restrict__ Wh,       // [256,1024]
                const float* __restrict__ Wa,       // [256,32]
                const float* __restrict__ ba,       // [32]
                const float* __restrict__ Wv,       // [256]
                const float* __restrict__ bv,       // [1]
                float*       __restrict__ out)      // [T,B,33]
{
    extern __shared__ float sm[];
    float* Wh_s = sm + SM_WH;
    float* hb   = sm + SM_HB;
    float* z_s  = sm + SM_Z;
    float* c_s  = sm + SM_C;
    float* Wo_s = sm + SM_WO;
    float* bo_s = sm + SM_BO;

    const int tid = threadIdx.x;
    uint32_t rank;
    asm("mov.u32 %0, %%cluster_ctarank;" : "=r"(rank));
    const int cl = blockIdx.x / CLUSTER;
    const int b0 = cl * NB;

    // --- preload Wh column slice: local col c -> global col 256*(c>>5) + 32*rank + (c&31)
    for (int idx = tid; idx < 256 * LC; idx += RTHREADS) {
        int k = idx >> 7;
        int c = idx & 127;
        int gcol = ((c >> 5) << 8) + ((int)rank << 5) + (c & 31);
        Wh_s[idx] = Wh[k * FOURH + gcol];
    }
    // --- preload carry_h into hbuf[1] (input buffer for t=0)
    for (int idx = tid; idx < NB * HID; idx += RTHREADS) {
        int b = idx >> 8;
        int k = idx & 255;
        hb[4096 + idx] = carry_h[(size_t)(b0 + b) * HID + k];
    }
    // --- preload carry_c slice
    for (int idx = tid; idx < NB * 32; idx += RTHREADS) {
        int b = idx >> 5;
        int j = idx & 31;
        c_s[idx] = carry_c[(size_t)(b0 + b) * HID + (int)rank * 32 + j];
    }
    // --- preload output-head columns: CTA r handles cols {r, r+8, r+16, r+24, [32 if r==0]}
    #pragma unroll
    for (int q = 0; q < 5; q++) {
        int col = (int)rank + 8 * q;
        if (col <= 32) {
            for (int k = tid; k < HID; k += RTHREADS)
                Wo_s[q * 256 + k] = (col < 32) ? Wa[k * NACT + col] : Wv[k];
            if (tid == 0) bo_s[q] = (col < 32) ? ba[col] : bv[0];
        }
    }
    __syncthreads();

    // matvec thread mapping: cp in [0,64) -> cols {2cp,2cp+1}; bq in [0,4) -> b {4bq..4bq+3}
    const int cp = tid & 63;
    const int bq = tid >> 6;
    const int wid  = tid >> 5;
    const int lane = tid & 31;
    const int ntask = (rank == 0) ? 80 : 64;   // q*16 + b tasks for output head

    for (int t = 0; t < T_STEPS; t++) {
        const int p_out = t & 1;
        const int p_in  = p_out ^ 1;
        float* hin  = hb + p_in  * 4096;
        float* hout = hb + p_out * 4096;

        // -- prefetch x_proj gate values for gating (hidden by matvec) --
        const size_t xbase = (size_t)t * BATCH * FOURH;
        float xi[2], xf[2], xg[2], xo[2];
        #pragma unroll
        for (int pp = 0; pp < 2; pp++) {
            int pr = tid + pp * 256;
            int b = pr >> 5, j = pr & 31;
            size_t base = xbase + (size_t)(b0 + b) * FOURH + (int)rank * 32 + j;
            xi[pp] = g_xproj[base];
            xf[pp] = g_xproj[base + 256];
            xg[pp] = g_xproj[base + 512];
            xo[pp] = g_xproj[base + 768];
        }

        // -- episode reset: zero h (local full copy) and c slice --
        {
            int b  = tid >> 4;
            int ch = tid & 15;
            int ep = epi[t * BATCH + b0 + b];
            if (ep) {
                float4 z4 = {0.f, 0.f, 0.f, 0.f};
                #pragma unroll
                for (int u = 0; u < 4; u++)
                    *(float4*)&hin[b * 256 + ch * 16 + u * 4] = z4;
                if (ch < 2) {
                    #pragma unroll
                    for (int u = 0; u < 4; u++)
                        *(float4*)&c_s[b * 32 + ch * 16 + u * 4] = z4;
                }
            }
        }
        __syncthreads();

        // -- z = h @ Wh_slice  (16 x 256) @ (256 x 128) --
        float acc[4][2];
        #pragma unroll
        for (int i = 0; i < 4; i++) { acc[i][0] = 0.f; acc[i][1] = 0.f; }

        for (int k = 0; k < 256; k += 4) {
            float4 h4[4];
            #pragma unroll
            for (int i = 0; i < 4; i++)
                h4[i] = *(const float4*)&hin[(bq * 4 + i) * 256 + k];
            #pragma unroll
            for (int kk = 0; kk < 4; kk++) {
                float2 w = *(const float2*)&Wh_s[(k + kk) * LC + cp * 2];
                #pragma unroll
                for (int i = 0; i < 4; i++) {
                    float hv = (kk == 0) ? h4[i].x : (kk == 1) ? h4[i].y
                             : (kk == 2) ? h4[i].z : h4[i].w;
                    acc[i][0] = fmaf(hv, w.x, acc[i][0]);
                    acc[i][1] = fmaf(hv, w.y, acc[i][1]);
                }
            }
        }
        #pragma unroll
        for (int i = 0; i < 4; i++) {
            float2 v; v.x = acc[i][0]; v.y = acc[i][1];
            *(float2*)&z_s[(bq * 4 + i) * LC + cp * 2] = v;
        }
        __syncthreads();

        // -- gating: each thread owns 2 (b, j) pairs --
        #pragma unroll
        for (int pp = 0; pp < 2; pp++) {
            int pr = tid + pp * 256;
            int b = pr >> 5, j = pr & 31;
            float iz = z_s[b * LC + j]      + xi[pp];
            float fz = z_s[b * LC + 32 + j] + xf[pp];
            float gz = z_s[b * LC + 64 + j] + xg[pp];
            float oz = z_s[b * LC + 96 + j] + xo[pp];
            float c_old = c_s[b * 32 + j];
            float nc = sigf(fz) * c_old + sigf(iz) * tanh_f(gz);
            float nh = sigf(oz) * tanh_f(nc);
            c_s[b * 32 + j] = nc;
            int hoff = b * 256 + (int)rank * 32 + j;
            hout[hoff] = nh;                          // local copy
            uint32_t saddr = smem_u32(&hout[hoff]);   // broadcast to peers
            #pragma unroll
            for (int rr = 0; rr < CLUSTER; rr++)
                if (rr != (int)rank) st_cluster_f32(saddr, rr, nh);
        }

        // -- cluster barrier: all h slices visible everywhere --
        asm volatile("barrier.cluster.arrive.aligned;" ::: "memory");
        asm volatile("barrier.cluster.wait.aligned;"   ::: "memory");

        // -- output head: out[t] = new_h @ [Wa | Wv] + [ba | bv] --
        for (int task = wid; task < ntask; task += 8) {
            int q = task >> 4;
            int b = task & 15;
            const float* hrow = &hout[b * 256];
            const float* wcol = &Wo_s[q * 256];
            float s = 0.f;
            #pragma unroll
            for (int u = 0; u < 8; u++)
                s = fmaf(hrow[lane + 32 * u], wcol[lane + 32 * u], s);
            #pragma unroll
            for (int off = 16; off; off >>= 1)
                s += __shfl_xor_sync(0xFFFFFFFFu, s, off);
            if (lane == 0) {
                int col = (int)rank + 8 * q;
                out[((size_t)t * BATCH + b0 + b) * OUTC + col] = s + bo_s[q];
            }
        }
        __syncthreads();   // protect hout reads before next iter's reset writes
    }
}

// ---------------------------------------------------------------------------
extern "C" void kernel_launch(void* const* d_in, const int* in_sizes, int n_in,
                              void* d_out, int out_size) {
    const float* inputs  = (const float*)d_in[0];
    const int*   epi     = (const int*)  d_in[1];
    const float* carry_c = (const float*)d_in[2];
    const float* carry_h = (const float*)d_in[3];
    const float* Wx      = (const float*)d_in[4];
    const float* Wh      = (const float*)d_in[5];
    const float* bias    = (const float*)d_in[6];
    const float* Wa      = (const float*)d_in[7];
    const float* ba      = (const float*)d_in[8];
    const float* Wv      = (const float*)d_in[9];
    const float* bv      = (const float*)d_in[10];
    float* out = (float*)d_out;

    cudaFuncSetAttribute(lstm_rec_kernel,
                         cudaFuncAttributeMaxDynamicSharedMemorySize, RSMEM_BYTES);

    dim3 g1(FOURH / BN, (T_STEPS * BATCH) / BM);  // (8, 1024)
    xproj_kernel<<<g1, 256>>>(inputs, Wx, bias);

    lstm_rec_kernel<<<(BATCH / NB) * CLUSTER, RTHREADS, RSMEM_BYTES>>>(
        epi, carry_c, carry_h, Wh, Wa, ba, Wv, bv, out);
}

// round 2
// speedup vs baseline: 1.1583x; 1.1583x over previous
#include <cuda_runtime.h>
#include <cuda_bf16.h>
#include <cstdint>
#include <cstddef>

// Problem dims
#define T_STEPS 512
#define BATCH   256
#define DIM     512
#define HID     256
#define FOURH   1024
#define NACT    32
#define OUTC    33

// Scratch for x_proj: [T, B, 4H] fp32 (device global, no runtime alloc)
__device__ float g_xproj[(size_t)T_STEPS * BATCH * FOURH];

// ===========================================================================
// Kernel 1: x_proj = inputs @ Wx + b   ([131072, 512] @ [512, 1024])
// Tensor-core bf16 split-precision GEMM (AhiBhi + AhiBlo + AloBhi), fp32 acc.
// Block tile 128x128x32, 8 warps (4M x 2N), warp tile 32x64.
// ===========================================================================
#define XBM 128
#define XBN 128
#define XBK 32
#define KPA 40     // A smem k-stride (bf16 elems), 80B = 5x16B -> conflict-free ldmatrix
#define NPB 136    // B smem n-stride (bf16 elems), 272B = 17x16B -> conflict-free ldmatrix

#define A_TERM_ELEMS (XBM * KPA)        // 5120
#define B_TERM_ELEMS (XBK * NPB)        // 4352
#define STAGE_ELEMS  (2 * A_TERM_ELEMS + 2 * B_TERM_ELEMS)   // 18944
#define XSMEM_BYTES  (2 * STAGE_ELEMS * 2)                    // 75776

__device__ __forceinline__ uint32_t smem_u32(const void* p) {
    uint32_t a;
    asm("{ .reg .u64 t; cvta.to.shared.u64 t, %1; cvt.u32.u64 %0, t; }"
        : "=r"(a) : "l"(p));
    return a;
}

__device__ __forceinline__ void ldsm_x4(uint32_t* r, uint32_t addr) {
    asm volatile("ldmatrix.sync.aligned.m8n8.x4.shared.b16 {%0,%1,%2,%3}, [%4];"
        : "=r"(r[0]), "=r"(r[1]), "=r"(r[2]), "=r"(r[3]) : "r"(addr));
}
__device__ __forceinline__ void ldsm_x4_t(uint32_t* r, uint32_t addr) {
    asm volatile("ldmatrix.sync.aligned.m8n8.x4.trans.shared.b16 {%0,%1,%2,%3}, [%4];"
        : "=r"(r[0]), "=r"(r[1]), "=r"(r[2]), "=r"(r[3]) : "r"(addr));
}
__device__ __forceinline__ void mma_bf16(float* c, const uint32_t* a,
                                         uint32_t b0, uint32_t b1) {
    asm volatile(
        "mma.sync.aligned.m16n8k16.row.col.f32.bf16.bf16.f32 "
        "{%0,%1,%2,%3}, {%4,%5,%6,%7}, {%8,%9}, {%0,%1,%2,%3};"
        : "+f"(c[0]), "+f"(c[1]), "+f"(c[2]), "+f"(c[3])
        : "r"(a[0]), "r"(a[1]), "r"(a[2]), "r"(a[3]), "r"(b0), "r"(b1));
}

__device__ __forceinline__ uint32_t pack2(__nv_bfloat16 a, __nv_bfloat16 b) {
    union { __nv_bfloat162 v; uint32_t u; } c;
    c.v = __nv_bfloat162(a, b);
    return c.u;
}

// Split one float4 into hi/lo bf16 pairs and store (ptrs are 4B-aligned elem ptrs)
__device__ __forceinline__ void split_store4(float4 v,
                                             __nv_bfloat16* hip,
                                             __nv_bfloat16* lop) {
    __nv_bfloat16 h0 = __float2bfloat16_rn(v.x);
    __nv_bfloat16 h1 = __float2bfloat16_rn(v.y);
    __nv_bfloat16 h2 = __float2bfloat16_rn(v.z);
    __nv_bfloat16 h3 = __float2bfloat16_rn(v.w);
    __nv_bfloat16 l0 = __float2bfloat16_rn(v.x - __bfloat162float(h0));
    __nv_bfloat16 l1 = __float2bfloat16_rn(v.y - __bfloat162float(h1));
    __nv_bfloat16 l2 = __float2bfloat16_rn(v.z - __bfloat162float(h2));
    __nv_bfloat16 l3 = __float2bfloat16_rn(v.w - __bfloat162float(h3));
    ((uint32_t*)hip)[0] = pack2(h0, h1);
    ((uint32_t*)hip)[1] = pack2(h2, h3);
    ((uint32_t*)lop)[0] = pack2(l0, l1);
    ((uint32_t*)lop)[1] = pack2(l2, l3);
}

__global__ __launch_bounds__(256) void xproj_mma_kernel(
    const float* __restrict__ A,      // [131072, 512]
    const float* __restrict__ W,      // [512, 1024]
    const float* __restrict__ bias)   // [1024]
{
    extern __shared__ __nv_bfloat16 xsm[];

    const int tid   = threadIdx.x;
    const int lane  = tid & 31;
    const int wid   = tid >> 5;
    const int warpM = wid & 3;        // 0..3
    const int warpN = wid >> 2;       // 0..1
    const int bM    = blockIdx.y;     // 0..1023
    const int bN    = blockIdx.x;     // 0..7

    // ---- global load mappings (per-thread, stage-invariant) ----
    // A: 1024 float4 per stage; thread handles idx = tid + 256*i, i=0..3
    const int arow0 = tid >> 3;       // + 32*i
    const int ac4   = tid & 7;
    // B: idx -> kr = (tid>>5) + 8*i, n4 = tid&31
    const int bkr0  = tid >> 5;
    const int bn4   = tid & 31;

    const float* Ag = A + (size_t)bM * XBM * DIM;
    const float* Wg = W + (size_t)bN * XBN;

    float acc[2][8][4];
    #pragma unroll
    for (int mt = 0; mt < 2; mt++)
        #pragma unroll
        for (int j = 0; j < 8; j++)
            #pragma unroll
            for (int q = 0; q < 4; q++) acc[mt][j][q] = 0.f;

    // ---- frag-load lane geometry ----
    const int a_row_l = (lane & 15);             // row within 16-row tile
    const int a_koff  = ((lane >> 4) << 3);      // 0 or 8
    const int b_krow  = (lane & 7) + ((lane >> 3) & 1) * 8;  // 0..15
    const int b_ncol  = ((lane >> 4) & 1) * 8;               // 0 or 8

    float4 aReg[4], bReg[4];

    // ---- prologue: load stage 0 ----
    #pragma unroll
    for (int i = 0; i < 4; i++) {
        aReg[i] = *(const float4*)(Ag + (size_t)(arow0 + 32 * i) * DIM + ac4 * 4);
        bReg[i] = *(const float4*)(Wg + (size_t)(bkr0 + 8 * i) * FOURH + bn4 * 4);
    }
    {
        __nv_bfloat16* Ahi = xsm;
        __nv_bfloat16* Alo = Ahi + A_TERM_ELEMS;
        __nv_bfloat16* Bhi = Alo + A_TERM_ELEMS;
        __nv_bfloat16* Blo = Bhi + B_TERM_ELEMS;
        #pragma unroll
        for (int i = 0; i < 4; i++) {
            int ar = arow0 + 32 * i;
            split_store4(aReg[i], &Ahi[ar * KPA + ac4 * 4], &Alo[ar * KPA + ac4 * 4]);
            int bk = bkr0 + 8 * i;
            split_store4(bReg[i], &Bhi[bk * NPB + bn4 * 4], &Blo[bk * NPB + bn4 * 4]);
        }
    }
    __syncthreads();

    const int NSTAGE = DIM / XBK;   // 16

    for (int s = 0; s < NSTAGE; s++) {
        // issue next-stage global loads early
        if (s + 1 < NSTAGE) {
            int k0 = (s + 1) * XBK;
            #pragma unroll
            for (int i = 0; i < 4; i++) {
                aReg[i] = *(const float4*)(Ag + (size_t)(arow0 + 32 * i) * DIM + k0 + ac4 * 4);
                bReg[i] = *(const float4*)(Wg + (size_t)(k0 + bkr0 + 8 * i) * FOURH + bn4 * 4);
            }
        }

        // compute from smem stage (s & 1)
        const __nv_bfloat16* st = xsm + (s & 1) * STAGE_ELEMS;
        uint32_t sAhi = smem_u32(st);
        uint32_t sAlo = sAhi + A_TERM_ELEMS * 2;
        uint32_t sBhi = sAlo + A_TERM_ELEMS * 2;
        uint32_t sBlo = sBhi + B_TERM_ELEMS * 2;

        #pragma unroll
        for (int ks = 0; ks < 2; ks++) {
            const int kk0 = ks * 16;
            uint32_t aHi[2][4], aLo[2][4];
            #pragma unroll
            for (int mt = 0; mt < 2; mt++) {
                uint32_t off =
                    (uint32_t)((warpM * 32 + mt * 16 + a_row_l) * KPA + kk0 + a_koff) * 2;
                ldsm_x4(aHi[mt], sAhi + off);
                ldsm_x4(aLo[mt], sAlo + off);
            }
            uint32_t bHi[4][4], bLo[4][4];
            #pragma unroll
            for (int nt = 0; nt < 4; nt++) {
                uint32_t off =
                    (uint32_t)((kk0 + b_krow) * NPB + warpN * 64 + nt * 16 + b_ncol) * 2;
                ldsm_x4_t(bHi[nt], sBhi + off);
                ldsm_x4_t(bLo[nt], sBlo + off);
            }
            #pragma unroll
            for (int mt = 0; mt < 2; mt++) {
                #pragma unroll
                for (int j = 0; j < 8; j++) {
                    uint32_t bh0 = bHi[j >> 1][(j & 1) * 2];
                    uint32_t bh1 = bHi[j >> 1][(j & 1) * 2 + 1];
                    uint32_t bl0 = bLo[j >> 1][(j & 1) * 2];
                    uint32_t bl1 = bLo[j >> 1][(j & 1) * 2 + 1];
                    mma_bf16(acc[mt][j], aHi[mt], bh0, bh1);
                    mma_bf16(acc[mt][j], aHi[mt], bl0, bl1);
                    mma_bf16(acc[mt][j], aLo[mt], bh0, bh1);
                }
            }
        }

        // stage the prefetched tile into the other smem buffer
        if (s + 1 < NSTAGE) {
            __nv_bfloat16* dst = xsm + ((s + 1) & 1) * STAGE_ELEMS;
            __nv_bfloat16* Ahi = dst;
            __nv_bfloat16* Alo = Ahi + A_TERM_ELEMS;
            __nv_bfloat16* Bhi = Alo + A_TERM_ELEMS;
            __nv_bfloat16* Blo = Bhi + B_TERM_ELEMS;
            #pragma unroll
            for (int i = 0; i < 4; i++) {
                int ar = arow0 + 32 * i;
                split_store4(aReg[i], &Ahi[ar * KPA + ac4 * 4], &Alo[ar * KPA + ac4 * 4]);
                int bk = bkr0 + 8 * i;
                split_store4(bReg[i], &Bhi[bk * NPB + bn4 * 4], &Blo[bk * NPB + bn4 * 4]);
            }
        }
        __syncthreads();
    }

    // ---- epilogue: add bias, write fp32 ----
    const int g  = lane >> 2;
    const int t2 = (lane & 3) * 2;
    #pragma unroll
    for (int mt = 0; mt < 2; mt++) {
        int row = bM * XBM + warpM * 32 + mt * 16 + g;
        #pragma unroll
        for (int j = 0; j < 8; j++) {
            int col = bN * XBN + warpN * 64 + j * 8 + t2;
            float b0 = bias[col], b1 = bias[col + 1];
            float2 o0 = make_float2(acc[mt][j][0] + b0, acc[mt][j][1] + b1);
            float2 o1 = make_float2(acc[mt][j][2] + b0, acc[mt][j][3] + b1);
            *(float2*)&g_xproj[(size_t)row * FOURH + col] = o0;
            *(float2*)&g_xproj[(size_t)(row + 8) * FOURH + col] = o1;
        }
    }
}

// ===========================================================================
// Kernel 2: persistent recurrent kernel (unchanged from R1 — passed).
// 16 clusters x 8 CTAs; Wh resident in SMEM; DSMEM h broadcast per step.
// ===========================================================================
#define CLUSTER 8
#define NB      16
#define LC      128
#define RTHREADS 256

#define SM_WH  0
#define SM_HB  32768
#define SM_Z   (SM_HB + 8192)
#define SM_C   (SM_Z + 2048)
#define SM_WO  (SM_C + 512)
#define SM_BO  (SM_WO + 1280)
#define SM_FLOATS (SM_BO + 8)
#define RSMEM_BYTES (SM_FLOATS * 4)

__device__ __forceinline__ void st_cluster_f32(uint32_t saddr, int rank, float v) {
    asm volatile(
        "{ .reg .b32 ra; mapa.shared::cluster.u32 ra, %0, %1;"
        "  st.shared::cluster.f32 [ra], %2; }"
        :: "r"(saddr), "r"(rank), "f"(v) : "memory");
}

__device__ __forceinline__ float sigf(float x) {
    return 1.f / (1.f + __expf(-x));
}
__device__ __forceinline__ float tanh_f(float x) {
    float e = __expf(-2.f * fabsf(x));
    float t = (1.f - e) / (1.f + e);
    return copysignf(t, x);
}

__global__ void __cluster_dims__(CLUSTER, 1, 1) __launch_bounds__(RTHREADS, 1)
lstm_rec_kernel(const int*   __restrict__ epi,
                const float* __restrict__ carry_c,
                const float* __restrict__ carry_h,
                const float* __restrict__ Wh,
                const float* __restrict__ Wa,
                const float* __restrict__ ba,
                const float* __restrict__ Wv,
                const float* __restrict__ bv,
                float*       __restrict__ out)
{
    extern __shared__ float sm[];
    float* Wh_s = sm + SM_WH;
    float* hb   = sm + SM_HB;
    float* z_s  = sm + SM_Z;
    float* c_s  = sm + SM_C;
    float* Wo_s = sm + SM_WO;
    float* bo_s = sm + SM_BO;

    const int tid = threadIdx.x;
    uint32_t rank;
    asm("mov.u32 %0, %%cluster_ctarank;" : "=r"(rank));
    const int cl = blockIdx.x / CLUSTER;
    const int b0 = cl * NB;

    for (int idx = tid; idx < 256 * LC; idx += RTHREADS) {
        int k = idx >> 7;
        int c = idx & 127;
        int gcol = ((c >> 5) << 8) + ((int)rank << 5) + (c & 31);
        Wh_s[idx] = Wh[k * FOURH + gcol];
    }
    for (int idx = tid; idx < NB * HID; idx += RTHREADS) {
        int b = idx >> 8;
        int k = idx & 255;
        hb[4096 + idx] = carry_h[(size_t)(b0 + b) * HID + k];
    }
    for (int idx = tid; idx < NB * 32; idx += RTHREADS) {
        int b = idx >> 5;
        int j = idx & 31;
        c_s[idx] = carry_c[(size_t)(b0 + b) * HID + (int)rank * 32 + j];
    }
    #pragma unroll
    for (int q = 0; q < 5; q++) {
        int col = (int)rank + 8 * q;
        if (col <= 32) {
            for (int k = tid; k < HID; k += RTHREADS)
                Wo_s[q * 256 + k] = (col < 32) ? Wa[k * NACT + col] : Wv[k];
            if (tid == 0) bo_s[q] = (col < 32) ? ba[col] : bv[0];
        }
    }
    __syncthreads();

    const int cp = tid & 63;
    const int bq = tid >> 6;
    const int wid  = tid >> 5;
    const int lane = tid & 31;
    const int ntask = (rank == 0) ? 80 : 64;

    for (int t = 0; t < T_STEPS; t++) {
        const int p_out = t & 1;
        const int p_in  = p_out ^ 1;
        float* hin  = hb + p_in  * 4096;
        float* hout = hb + p_out * 4096;

        const size_t xbase = (size_t)t * BATCH * FOURH;
        float xi[2], xf[2], xg[2], xo[2];
        #pragma unroll
        for (int pp = 0; pp < 2; pp++) {
            int pr = tid + pp * 256;
            int b = pr >> 5, j = pr & 31;
            size_t base = xbase + (size_t)(b0 + b) * FOURH + (int)rank * 32 + j;
            xi[pp] = g_xproj[base];
            xf[pp] = g_xproj[base + 256];
            xg[pp] = g_xproj[base + 512];
            xo[pp] = g_xproj[base + 768];
        }

        {
            int b  = tid >> 4;
            int ch = tid & 15;
            int ep = epi[t * BATCH + b0 + b];
            if (ep) {
                float4 z4 = {0.f, 0.f, 0.f, 0.f};
                #pragma unroll
                for (int u = 0; u < 4; u++)
                    *(float4*)&hin[b * 256 + ch * 16 + u * 4] = z4;
                if (ch < 2) {
                    #pragma unroll
                    for (int u = 0; u < 4; u++)
                        *(float4*)&c_s[b * 32 + ch * 16 + u * 4] = z4;
                }
            }
        }
        __syncthreads();

        float acc[4][2];
        #pragma unroll
        for (int i = 0; i < 4; i++) { acc[i][0] = 0.f; acc[i][1] = 0.f; }

        for (int k = 0; k < 256; k += 4) {
            float4 h4[4];
            #pragma unroll
            for (int i = 0; i < 4; i++)
                h4[i] = *(const float4*)&hin[(bq * 4 + i) * 256 + k];
            #pragma unroll
            for (int kk = 0; kk < 4; kk++) {
                float2 w = *(const float2*)&Wh_s[(k + kk) * LC + cp * 2];
                #pragma unroll
                for (int i = 0; i < 4; i++) {
                    float hv = (kk == 0) ? h4[i].x : (kk == 1) ? h4[i].y
                             : (kk == 2) ? h4[i].z : h4[i].w;
                    acc[i][0] = fmaf(hv, w.x, acc[i][0]);
                    acc[i][1] = fmaf(hv, w.y, acc[i][1]);
                }
            }
        }
        #pragma unroll
        for (int i = 0; i < 4; i++) {
            float2 v; v.x = acc[i][0]; v.y = acc[i][1];
            *(float2*)&z_s[(bq * 4 + i) * LC + cp * 2] = v;
        }
        __syncthreads();

        #pragma unroll
        for (int pp = 0; pp < 2; pp++) {
            int pr = tid + pp * 256;
            int b = pr >> 5, j = pr & 31;
            float iz = z_s[b * LC + j]      + xi[pp];
            float fz = z_s[b * LC + 32 + j] + xf[pp];
            float gz = z_s[b * LC + 64 + j] + xg[pp];
            float oz = z_s[b * LC + 96 + j] + xo[pp];
            float c_old = c_s[b * 32 + j];
            float nc = sigf(fz) * c_old + sigf(iz) * tanh_f(gz);
            float nh = sigf(oz) * tanh_f(nc);
            c_s[b * 32 + j] = nc;
            int hoff = b * 256 + (int)rank * 32 + j;
            hout[hoff] = nh;
            uint32_t saddr = smem_u32(&hout[hoff]);
            #pragma unroll
            for (int rr = 0; rr < CLUSTER; rr++)
                if (rr != (int)rank) st_cluster_f32(saddr, rr, nh);
        }

        asm volatile("barrier.cluster.arrive.aligned;" ::: "memory");
        asm volatile("barrier.cluster.wait.aligned;"   ::: "memory");

        for (int task = wid; task < ntask; task += 8) {
            int q = task >> 4;
            int b = task & 15;
            const float* hrow = &hout[b * 256];
            const float* wcol = &Wo_s[q * 256];
            float s = 0.f;
            #pragma unroll
            for (int u = 0; u < 8; u++)
                s = fmaf(hrow[lane + 32 * u], wcol[lane + 32 * u], s);
            #pragma unroll
            for (int off = 16; off; off >>= 1)
                s += __shfl_xor_sync(0xFFFFFFFFu, s, off);
            if (lane == 0) {
                int col = (int)rank + 8 * q;
                out[((size_t)t * BATCH + b0 + b) * OUTC + col] = s + bo_s[q];
            }
        }
        __syncthreads();
    }
}

// ---------------------------------------------------------------------------
extern "C" void kernel_launch(void* const* d_in, const int* in_sizes, int n_in,
                              void* d_out, int out_size) {
    const float* inputs  = (const float*)d_in[0];
    const int*   epi     = (const int*)  d_in[1];
    const float* carry_c = (const float*)d_in[2];
    const float* carry_h = (const float*)d_in[3];
    const float* Wx      = (const float*)d_in[4];
    const float* Wh      = (const float*)d_in[5];
    const float* bias    = (const float*)d_in[6];
    const float* Wa      = (const float*)d_in[7];
    const float* ba      = (const float*)d_in[8];
    const float* Wv      = (const float*)d_in[9];
    const float* bv      = (const float*)d_in[10];
    float* out = (float*)d_out;

    cudaFuncSetAttribute(xproj_mma_kernel,
                         cudaFuncAttributeMaxDynamicSharedMemorySize, XSMEM_BYTES);
    cudaFuncSetAttribute(lstm_rec_kernel,
                         cudaFuncAttributeMaxDynamicSharedMemorySize, RSMEM_BYTES);

    dim3 g1(FOURH / XBN, (T_STEPS * BATCH) / XBM);  // (8, 1024)
    xproj_mma_kernel<<<g1, 256, XSMEM_BYTES>>>(inputs, Wx, bias);

    lstm_rec_kernel<<<(BATCH / NB) * CLUSTER, RTHREADS, RSMEM_BYTES>>>(
        epi, carry_c, carry_h, Wh, Wa, ba, Wv, bv, out);
}

// round 3
// speedup vs baseline: 1.6639x; 1.4366x over previous
#include <cuda_runtime.h>
#include <cuda_bf16.h>
#include <cstdint>
#include <cstddef>

// Problem dims
#define T_STEPS 512
#define BATCH   256
#define DIM     512
#define HID     256
#define FOURH   1024
#define NACT    32
#define OUTC    33

// Scratch for x_proj: [T, B, 4H] fp32
__device__ float g_xproj[(size_t)T_STEPS * BATCH * FOURH];

// ===========================================================================
// Shared helpers
// ===========================================================================
__device__ __forceinline__ uint32_t smem_u32(const void* p) {
    uint32_t a;
    asm("{ .reg .u64 t; cvta.to.shared.u64 t, %1; cvt.u32.u64 %0, t; }"
        : "=r"(a) : "l"(p));
    return a;
}
__device__ __forceinline__ void ldsm_x4(uint32_t* r, uint32_t addr) {
    asm volatile("ldmatrix.sync.aligned.m8n8.x4.shared.b16 {%0,%1,%2,%3}, [%4];"
        : "=r"(r[0]), "=r"(r[1]), "=r"(r[2]), "=r"(r[3]) : "r"(addr));
}
__device__ __forceinline__ void ldsm_x4_t(uint32_t* r, uint32_t addr) {
    asm volatile("ldmatrix.sync.aligned.m8n8.x4.trans.shared.b16 {%0,%1,%2,%3}, [%4];"
        : "=r"(r[0]), "=r"(r[1]), "=r"(r[2]), "=r"(r[3]) : "r"(addr));
}
__device__ __forceinline__ void mma_bf16(float* c, const uint32_t* a,
                                         uint32_t b0, uint32_t b1) {
    asm volatile(
        "mma.sync.aligned.m16n8k16.row.col.f32.bf16.bf16.f32 "
        "{%0,%1,%2,%3}, {%4,%5,%6,%7}, {%8,%9}, {%0,%1,%2,%3};"
        : "+f"(c[0]), "+f"(c[1]), "+f"(c[2]), "+f"(c[3])
        : "r"(a[0]), "r"(a[1]), "r"(a[2]), "r"(a[3]), "r"(b0), "r"(b1));
}
__device__ __forceinline__ uint32_t pack2(__nv_bfloat16 a, __nv_bfloat16 b) {
    union { __nv_bfloat162 v; uint32_t u; } c;
    c.v = __nv_bfloat162(a, b);
    return c.u;
}
__device__ __forceinline__ void split_store4(float4 v,
                                             __nv_bfloat16* hip,
                                             __nv_bfloat16* lop) {
    __nv_bfloat16 h0 = __float2bfloat16_rn(v.x);
    __nv_bfloat16 h1 = __float2bfloat16_rn(v.y);
    __nv_bfloat16 h2 = __float2bfloat16_rn(v.z);
    __nv_bfloat16 h3 = __float2bfloat16_rn(v.w);
    __nv_bfloat16 l0 = __float2bfloat16_rn(v.x - __bfloat162float(h0));
    __nv_bfloat16 l1 = __float2bfloat16_rn(v.y - __bfloat162float(h1));
    __nv_bfloat16 l2 = __float2bfloat16_rn(v.z - __bfloat162float(h2));
    __nv_bfloat16 l3 = __float2bfloat16_rn(v.w - __bfloat162float(h3));
    ((uint32_t*)hip)[0] = pack2(h0, h1);
    ((uint32_t*)hip)[1] = pack2(h2, h3);
    ((uint32_t*)lop)[0] = pack2(l0, l1);
    ((uint32_t*)lop)[1] = pack2(l2, l3);
}

// ===========================================================================
// Kernel 1: x_proj = inputs @ Wx + b (unchanged from R2 — measured ~1.2 ms)
// ===========================================================================
#define XBM 128
#define XBN 128
#define XBK 32
#define KPA 40
#define NPB 136
#define A_TERM_ELEMS (XBM * KPA)
#define B_TERM_ELEMS (XBK * NPB)
#define STAGE_ELEMS  (2 * A_TERM_ELEMS + 2 * B_TERM_ELEMS)
#define XSMEM_BYTES  (2 * STAGE_ELEMS * 2)

__global__ __launch_bounds__(256) void xproj_mma_kernel(
    const float* __restrict__ A,
    const float* __restrict__ W,
    const float* __restrict__ bias)
{
    extern __shared__ __nv_bfloat16 xsm[];

    const int tid   = threadIdx.x;
    const int lane  = tid & 31;
    const int wid   = tid >> 5;
    const int warpM = wid & 3;
    const int warpN = wid >> 2;
    const int bM    = blockIdx.y;
    const int bN    = blockIdx.x;

    const int arow0 = tid >> 3;
    const int ac4   = tid & 7;
    const int bkr0  = tid >> 5;
    const int bn4   = tid & 31;

    const float* Ag = A + (size_t)bM * XBM * DIM;
    const float* Wg = W + (size_t)bN * XBN;

    float acc[2][8][4];
    #pragma unroll
    for (int mt = 0; mt < 2; mt++)
        #pragma unroll
        for (int j = 0; j < 8; j++)
            #pragma unroll
            for (int q = 0; q < 4; q++) acc[mt][j][q] = 0.f;

    const int a_row_l = (lane & 15);
    const int a_koff  = ((lane >> 4) << 3);
    const int b_krow  = (lane & 7) + ((lane >> 3) & 1) * 8;
    const int b_ncol  = ((lane >> 4) & 1) * 8;

    float4 aReg[4], bReg[4];

    #pragma unroll
    for (int i = 0; i < 4; i++) {
        aReg[i] = *(const float4*)(Ag + (size_t)(arow0 + 32 * i) * DIM + ac4 * 4);
        bReg[i] = *(const float4*)(Wg + (size_t)(bkr0 + 8 * i) * FOURH + bn4 * 4);
    }
    {
        __nv_bfloat16* Ahi = xsm;
        __nv_bfloat16* Alo = Ahi + A_TERM_ELEMS;
        __nv_bfloat16* Bhi = Alo + A_TERM_ELEMS;
        __nv_bfloat16* Blo = Bhi + B_TERM_ELEMS;
        #pragma unroll
        for (int i = 0; i < 4; i++) {
            int ar = arow0 + 32 * i;
            split_store4(aReg[i], &Ahi[ar * KPA + ac4 * 4], &Alo[ar * KPA + ac4 * 4]);
            int bk = bkr0 + 8 * i;
            split_store4(bReg[i], &Bhi[bk * NPB + bn4 * 4], &Blo[bk * NPB + bn4 * 4]);
        }
    }
    __syncthreads();

    const int NSTAGE = DIM / XBK;

    for (int s = 0; s < NSTAGE; s++) {
        if (s + 1 < NSTAGE) {
            int k0 = (s + 1) * XBK;
            #pragma unroll
            for (int i = 0; i < 4; i++) {
                aReg[i] = *(const float4*)(Ag + (size_t)(arow0 + 32 * i) * DIM + k0 + ac4 * 4);
                bReg[i] = *(const float4*)(Wg + (size_t)(k0 + bkr0 + 8 * i) * FOURH + bn4 * 4);
            }
        }

        const __nv_bfloat16* st = xsm + (s & 1) * STAGE_ELEMS;
        uint32_t sAhi = smem_u32(st);
        uint32_t sAlo = sAhi + A_TERM_ELEMS * 2;
        uint32_t sBhi = sAlo + A_TERM_ELEMS * 2;
        uint32_t sBlo = sBhi + B_TERM_ELEMS * 2;

        #pragma unroll
        for (int ks = 0; ks < 2; ks++) {
            const int kk0 = ks * 16;
            uint32_t aHi[2][4], aLo[2][4];
            #pragma unroll
            for (int mt = 0; mt < 2; mt++) {
                uint32_t off =
                    (uint32_t)((warpM * 32 + mt * 16 + a_row_l) * KPA + kk0 + a_koff) * 2;
                ldsm_x4(aHi[mt], sAhi + off);
                ldsm_x4(aLo[mt], sAlo + off);
            }
            uint32_t bHi[4][4], bLo[4][4];
            #pragma unroll
            for (int nt = 0; nt < 4; nt++) {
                uint32_t off =
                    (uint32_t)((kk0 + b_krow) * NPB + warpN * 64 + nt * 16 + b_ncol) * 2;
                ldsm_x4_t(bHi[nt], sBhi + off);
                ldsm_x4_t(bLo[nt], sBlo + off);
            }
            #pragma unroll
            for (int mt = 0; mt < 2; mt++) {
                #pragma unroll
                for (int j = 0; j < 8; j++) {
                    uint32_t bh0 = bHi[j >> 1][(j & 1) * 2];
                    uint32_t bh1 = bHi[j >> 1][(j & 1) * 2 + 1];
                    uint32_t bl0 = bLo[j >> 1][(j & 1) * 2];
                    uint32_t bl1 = bLo[j >> 1][(j & 1) * 2 + 1];
                    mma_bf16(acc[mt][j], aHi[mt], bh0, bh1);
                    mma_bf16(acc[mt][j], aHi[mt], bl0, bl1);
                    mma_bf16(acc[mt][j], aLo[mt], bh0, bh1);
                }
            }
        }

        if (s + 1 < NSTAGE) {
            __nv_bfloat16* dst = xsm + ((s + 1) & 1) * STAGE_ELEMS;
            __nv_bfloat16* Ahi = dst;
            __nv_bfloat16* Alo = Ahi + A_TERM_ELEMS;
            __nv_bfloat16* Bhi = Alo + A_TERM_ELEMS;
            __nv_bfloat16* Blo = Bhi + B_TERM_ELEMS;
            #pragma unroll
            for (int i = 0; i < 4; i++) {
                int ar = arow0 + 32 * i;
                split_store4(aReg[i], &Ahi[ar * KPA + ac4 * 4], &Alo[ar * KPA + ac4 * 4]);
                int bk = bkr0 + 8 * i;
                split_store4(bReg[i], &Bhi[bk * NPB + bn4 * 4], &Blo[bk * NPB + bn4 * 4]);
            }
        }
        __syncthreads();
    }

    const int g  = lane >> 2;
    const int t2 = (lane & 3) * 2;
    #pragma unroll
    for (int mt = 0; mt < 2; mt++) {
        int row = bM * XBM + warpM * 32 + mt * 16 + g;
        #pragma unroll
        for (int j = 0; j < 8; j++) {
            int col = bN * XBN + warpN * 64 + j * 8 + t2;
            float b0 = bias[col], b1 = bias[col + 1];
            float2 o0 = make_float2(acc[mt][j][0] + b0, acc[mt][j][1] + b1);
            float2 o1 = make_float2(acc[mt][j][2] + b0, acc[mt][j][3] + b1);
            *(float2*)&g_xproj[(size_t)row * FOURH + col] = o0;
            *(float2*)&g_xproj[(size_t)(row + 8) * FOURH + col] = o1;
        }
    }
}

// ===========================================================================
// Kernel 2: recurrent kernel — tensor-core matvec + vectorized DSMEM bcast.
// 16 clusters x 8 CTAs. Wh resident as split bf16 (hi/lo). h carried as
// split bf16. Per step: mma(16x128x256, 3 terms) -> gating -> vector bcast.
// ===========================================================================
#define CLUSTER 8
#define NB      16
#define LC      128
#define RTHREADS 256

#define HSTRIDE 264      // bf16 elems per h row (pad; 528B = 33x16B)
#define WSTRIDE 136      // bf16 elems per Wh row (272B = 17x16B)
#define ZSTRIDE 132      // floats per z row

// byte offsets in dynamic smem
#define SMB_WHHI 0
#define SMB_WHLO (SMB_WHHI + 256 * WSTRIDE * 2)        // 69632
#define SMB_HB   (SMB_WHLO + 256 * WSTRIDE * 2)        // 139264
// hb layout: [buf(2)][arr(2: hi,lo)][16][HSTRIDE] bf16
#define HB_ARR_BYTES (NB * HSTRIDE * 2)                 // 8448
#define HB_BUF_BYTES (2 * HB_ARR_BYTES)                 // 16896
#define SMB_Z    (SMB_HB + 2 * HB_BUF_BYTES)            // 173056
#define SMB_C    (SMB_Z + NB * ZSTRIDE * 4)             // 181504
#define SMB_WO   (SMB_C + NB * 32 * 4)                  // 183552
#define SMB_BO   (SMB_WO + 5 * 256 * 4)                 // 188672
#define RSMEM_BYTES (SMB_BO + 32)                       // 188704

__device__ __forceinline__ void st_cluster_v4(uint32_t saddr, int rank,
                                              uint32_t a, uint32_t b,
                                              uint32_t c, uint32_t d) {
    asm volatile(
        "{ .reg .b32 ra; mapa.shared::cluster.u32 ra, %0, %1;"
        "  st.shared::cluster.v4.b32 [ra], {%2,%3,%4,%5}; }"
        :: "r"(saddr), "r"(rank), "r"(a), "r"(b), "r"(c), "r"(d) : "memory");
}

__device__ __forceinline__ float sigf(float x) {
    return 1.f / (1.f + __expf(-x));
}
__device__ __forceinline__ float tanh_f(float x) {
    float e = __expf(-2.f * fabsf(x));
    float t = (1.f - e) / (1.f + e);
    return copysignf(t, x);
}

__global__ void __cluster_dims__(CLUSTER, 1, 1) __launch_bounds__(RTHREADS, 1)
lstm_rec_kernel(const int*   __restrict__ epi,
                const float* __restrict__ carry_c,
                const float* __restrict__ carry_h,
                const float* __restrict__ Wh,
                const float* __restrict__ Wa,
                const float* __restrict__ ba,
                const float* __restrict__ Wv,
                const float* __restrict__ bv,
                float*       __restrict__ out)
{
    extern __shared__ char smraw[];
    __nv_bfloat16* WhHi = (__nv_bfloat16*)(smraw + SMB_WHHI);
    __nv_bfloat16* WhLo = (__nv_bfloat16*)(smraw + SMB_WHLO);
    float* z_s  = (float*)(smraw + SMB_Z);
    float* c_s  = (float*)(smraw + SMB_C);
    float* Wo_s = (float*)(smraw + SMB_WO);
    float* bo_s = (float*)(smraw + SMB_BO);

    const int tid  = threadIdx.x;
    const int lane = tid & 31;
    const int wid  = tid >> 5;
    uint32_t rank;
    asm("mov.u32 %0, %%cluster_ctarank;" : "=r"(rank));
    const int cl = blockIdx.x / CLUSTER;
    const int b0 = cl * NB;

    // --- preload Wh slice, split into bf16 hi/lo.
    // local col c -> global col ((c>>5)<<8) + rank*32 + (c&31)
    for (int idx = tid; idx < 256 * LC; idx += RTHREADS) {
        int k = idx >> 7;
        int c = idx & 127;
        int gcol = ((c >> 5) << 8) + ((int)rank << 5) + (c & 31);
        float w = Wh[k * FOURH + gcol];
        __nv_bfloat16 hi = __float2bfloat16_rn(w);
        __nv_bfloat16 lo = __float2bfloat16_rn(w - __bfloat162float(hi));
        WhHi[k * WSTRIDE + c] = hi;
        WhLo[k * WSTRIDE + c] = lo;
    }
    // --- preload carry_h into buffer 1 (input buffer for t=0), split bf16
    for (int idx = tid; idx < NB * HID; idx += RTHREADS) {
        int b = idx >> 8;
        int k = idx & 255;
        float v = carry_h[(size_t)(b0 + b) * HID + k];
        __nv_bfloat16 hi = __float2bfloat16_rn(v);
        __nv_bfloat16 lo = __float2bfloat16_rn(v - __bfloat162float(hi));
        __nv_bfloat16* hHi = (__nv_bfloat16*)(smraw + SMB_HB + 1 * HB_BUF_BYTES);
        __nv_bfloat16* hLo = hHi + NB * HSTRIDE;
        hHi[b * HSTRIDE + k] = hi;
        hLo[b * HSTRIDE + k] = lo;
    }
    // --- preload carry_c slice
    for (int idx = tid; idx < NB * 32; idx += RTHREADS) {
        int b = idx >> 5;
        int j = idx & 31;
        c_s[idx] = carry_c[(size_t)(b0 + b) * HID + (int)rank * 32 + j];
    }
    // --- preload output-head columns
    #pragma unroll
    for (int q = 0; q < 5; q++) {
        int col = (int)rank + 8 * q;
        if (col <= 32) {
            for (int k = tid; k < HID; k += RTHREADS)
                Wo_s[q * 256 + k] = (col < 32) ? Wa[k * NACT + col] : Wv[k];
            if (tid == 0) bo_s[q] = (col < 32) ? ba[col] : bv[0];
        }
    }
    __syncthreads();

    // frag lane geometry (same proven pattern as xproj)
    const int a_row_l = (lane & 15);
    const int a_koff  = ((lane >> 4) << 3);
    const int b_krow  = (lane & 7) + ((lane >> 3) & 1) * 8;
    const int b_ncol  = ((lane >> 4) & 1) * 8;

    const uint32_t sWhHi = smem_u32(WhHi);
    const uint32_t sWhLo = smem_u32(WhLo);

    const int ntask = (rank == 0) ? 80 : 64;

    // epi prefetch (b = tid>>4 used by reset)
    int ep_reg = epi[0 * BATCH + b0 + (tid >> 4)];

    for (int t = 0; t < T_STEPS; t++) {
        const int p_out = t & 1;
        const int p_in  = p_out ^ 1;
        __nv_bfloat16* hinHi  = (__nv_bfloat16*)(smraw + SMB_HB + p_in * HB_BUF_BYTES);
        __nv_bfloat16* hinLo  = hinHi + NB * HSTRIDE;
        __nv_bfloat16* houtHi = (__nv_bfloat16*)(smraw + SMB_HB + p_out * HB_BUF_BYTES);
        __nv_bfloat16* houtLo = houtHi + NB * HSTRIDE;

        // -- prefetch x_proj gate values (consumed at gating, hidden by mma) --
        const size_t xbase = (size_t)t * BATCH * FOURH;
        float xi[2], xf[2], xg[2], xo[2];
        #pragma unroll
        for (int pp = 0; pp < 2; pp++) {
            int pr = tid + pp * 256;
            int b = pr >> 5, j = pr & 31;
            size_t base = xbase + (size_t)(b0 + b) * FOURH + (int)rank * 32 + j;
            xi[pp] = g_xproj[base];
            xf[pp] = g_xproj[base + 256];
            xg[pp] = g_xproj[base + 512];
            xo[pp] = g_xproj[base + 768];
        }

        // -- episode reset: zero full hin row (both arrays) and c slice --
        {
            int b  = tid >> 4;
            int ch = tid & 15;
            if (ep_reg) {
                uint4 z4 = {0u, 0u, 0u, 0u};
                *(uint4*)&hinHi[b * HSTRIDE + ch * 16]     = z4;
                *(uint4*)&hinHi[b * HSTRIDE + ch * 16 + 8] = z4;
                *(uint4*)&hinLo[b * HSTRIDE + ch * 16]     = z4;
                *(uint4*)&hinLo[b * HSTRIDE + ch * 16 + 8] = z4;
                if (ch < 2) {
                    float4 zf = {0.f, 0.f, 0.f, 0.f};
                    #pragma unroll
                    for (int u = 0; u < 4; u++)
                        *(float4*)&c_s[b * 32 + ch * 16 + u * 4] = zf;
                }
            }
        }
        __syncthreads();

        // -- z = h @ Wh_slice via mma: M=16, N=128 (16/warp), K=256 --
        {
            const uint32_t sHinHi = smem_u32(hinHi);
            const uint32_t sHinLo = smem_u32(hinLo);
            float acc[2][4];
            #pragma unroll
            for (int t2 = 0; t2 < 2; t2++)
                #pragma unroll
                for (int q = 0; q < 4; q++) acc[t2][q] = 0.f;

            #pragma unroll 4
            for (int ks = 0; ks < 16; ks++) {
                const int kk0 = ks * 16;
                uint32_t aoff = (uint32_t)(a_row_l * HSTRIDE + kk0 + a_koff) * 2;
                uint32_t aHi[4], aLo[4];
                ldsm_x4(aHi, sHinHi + aoff);
                ldsm_x4(aLo, sHinLo + aoff);
                uint32_t boff =
                    (uint32_t)((kk0 + b_krow) * WSTRIDE + wid * 16 + b_ncol) * 2;
                uint32_t bHi[4], bLo[4];
                ldsm_x4_t(bHi, sWhHi + boff);
                ldsm_x4_t(bLo, sWhLo + boff);
                #pragma unroll
                for (int t2 = 0; t2 < 2; t2++) {
                    mma_bf16(acc[t2], aHi, bHi[t2 * 2], bHi[t2 * 2 + 1]);
                    mma_bf16(acc[t2], aHi, bLo[t2 * 2], bLo[t2 * 2 + 1]);
                    mma_bf16(acc[t2], aLo, bHi[t2 * 2], bHi[t2 * 2 + 1]);
                }
            }
            // write z to smem: rows = batch, cols = local gate cols
            int r0 = lane >> 2;
            int cb = wid * 16 + 2 * (lane & 3);
            #pragma unroll
            for (int t2 = 0; t2 < 2; t2++) {
                int col = cb + 8 * t2;
                *(float2*)&z_s[r0 * ZSTRIDE + col] =
                    make_float2(acc[t2][0], acc[t2][1]);
                *(float2*)&z_s[(r0 + 8) * ZSTRIDE + col] =
                    make_float2(acc[t2][2], acc[t2][3]);
            }
        }

        // prefetch epi for next step
        if (t + 1 < T_STEPS)
            ep_reg = epi[(t + 1) * BATCH + b0 + (tid >> 4)];

        __syncthreads();

        // -- gating: each thread owns 2 (b, j) pairs; write split bf16 local --
        #pragma unroll
        for (int pp = 0; pp < 2; pp++) {
            int pr = tid + pp * 256;
            int b = pr >> 5, j = pr & 31;
            float iz = z_s[b * ZSTRIDE + j]      + xi[pp];
            float fz = z_s[b * ZSTRIDE + 32 + j] + xf[pp];
            float gz = z_s[b * ZSTRIDE + 64 + j] + xg[pp];
            float oz = z_s[b * ZSTRIDE + 96 + j] + xo[pp];
            float c_old = c_s[b * 32 + j];
            float nc = sigf(fz) * c_old + sigf(iz) * tanh_f(gz);
            float nh = sigf(oz) * tanh_f(nc);
            c_s[b * 32 + j] = nc;
            __nv_bfloat16 hi = __float2bfloat16_rn(nh);
            __nv_bfloat16 lo = __float2bfloat16_rn(nh - __bfloat162float(hi));
            int hoff = b * HSTRIDE + (int)rank * 32 + j;
            houtHi[hoff] = hi;
            houtLo[hoff] = lo;
        }
        __syncthreads();

        // -- vectorized DSMEM broadcast of local slice (2 KB as 128 x 16B) --
        if (tid < 128) {
            int arr = tid >> 6;          // 0 = hi, 1 = lo
            int row = (tid >> 2) & 15;
            int seg = tid & 3;
            __nv_bfloat16* base = arr ? houtLo : houtHi;
            uint32_t saddr = smem_u32(base) +
                             (uint32_t)(row * HSTRIDE + (int)rank * 32) * 2 + seg * 16;
            uint4 v = *(const uint4*)((const char*)base +
                         (size_t)(row * HSTRIDE + (int)rank * 32) * 2 + seg * 16);
            #pragma unroll
            for (int rr = 0; rr < CLUSTER; rr++)
                if (rr != (int)rank)
                    st_cluster_v4(saddr, rr, v.x, v.y, v.z, v.w);
        }

        // -- cluster barrier: all h slices visible everywhere --
        asm volatile("barrier.cluster.arrive.aligned;" ::: "memory");
        asm volatile("barrier.cluster.wait.aligned;"   ::: "memory");

        // -- output head: out[t] = new_h @ [Wa | Wv] + [ba | bv] --
        for (int task = wid; task < ntask; task += 8) {
            int q = task >> 4;
            int b = task & 15;
            const __nv_bfloat16* hHr = &houtHi[b * HSTRIDE];
            const __nv_bfloat16* hLr = &houtLo[b * HSTRIDE];
            const float* wcol = &Wo_s[q * 256];
            float s = 0.f;
            #pragma unroll
            for (int u = 0; u < 8; u++) {
                int k = lane + 32 * u;
                float hv = __bfloat162float(hHr[k]) + __bfloat162float(hLr[k]);
                s = fmaf(hv, wcol[k], s);
            }
            #pragma unroll
            for (int off = 16; off; off >>= 1)
                s += __shfl_xor_sync(0xFFFFFFFFu, s, off);
            if (lane == 0) {
                int col = (int)rank + 8 * q;
                out[((size_t)t * BATCH + b0 + b) * OUTC + col] = s + bo_s[q];
            }
        }
        __syncthreads();   // protect hout reads before next iter's reset writes
    }
}

// ---------------------------------------------------------------------------
extern "C" void kernel_launch(void* const* d_in, const int* in_sizes, int n_in,
                              void* d_out, int out_size) {
    const float* inputs  = (const float*)d_in[0];
    const int*   epi     = (const int*)  d_in[1];
    const float* carry_c = (const float*)d_in[2];
    const float* carry_h = (const float*)d_in[3];
    const float* Wx      = (const float*)d_in[4];
    const float* Wh      = (const float*)d_in[5];
    const float* bias    = (const float*)d_in[6];
    const float* Wa      = (const float*)d_in[7];
    const float* ba      = (const float*)d_in[8];
    const float* Wv      = (const float*)d_in[9];
    const float* bv      = (const float*)d_in[10];
    float* out = (float*)d_out;

    cudaFuncSetAttribute(xproj_mma_kernel,
                         cudaFuncAttributeMaxDynamicSharedMemorySize, XSMEM_BYTES);
    cudaFuncSetAttribute(lstm_rec_kernel,
                         cudaFuncAttributeMaxDynamicSharedMemorySize, RSMEM_BYTES);

    dim3 g1(FOURH / XBN, (T_STEPS * BATCH) / XBM);
    xproj_mma_kernel<<<g1, 256, XSMEM_BYTES>>>(inputs, Wx, bias);

    lstm_rec_kernel<<<(BATCH / NB) * CLUSTER, RTHREADS, RSMEM_BYTES>>>(
        epi, carry_c, carry_h, Wh, Wa, ba, Wv, bv, out);
}

// round 4
// speedup vs baseline: 2.2333x; 1.3422x over previous
#include <cuda_runtime.h>
#include <cuda_bf16.h>
#include <cstdint>
#include <cstddef>

// Problem dims
#define T_STEPS 512
#define BATCH   256
#define DIM     512
#define HID     256
#define FOURH   1024
#define NACT    32
#define OUTC    33

// Scratch for x_proj: [T, B, 4H] fp32
__device__ float g_xproj[(size_t)T_STEPS * BATCH * FOURH];

// ===========================================================================
// Shared helpers
// ===========================================================================
__device__ __forceinline__ uint32_t smem_u32(const void* p) {
    uint32_t a;
    asm("{ .reg .u64 t; cvta.to.shared.u64 t, %1; cvt.u32.u64 %0, t; }"
        : "=r"(a) : "l"(p));
    return a;
}
__device__ __forceinline__ void ldsm_x4(uint32_t* r, uint32_t addr) {
    asm volatile("ldmatrix.sync.aligned.m8n8.x4.shared.b16 {%0,%1,%2,%3}, [%4];"
        : "=r"(r[0]), "=r"(r[1]), "=r"(r[2]), "=r"(r[3]) : "r"(addr));
}
__device__ __forceinline__ void ldsm_x4_t(uint32_t* r, uint32_t addr) {
    asm volatile("ldmatrix.sync.aligned.m8n8.x4.trans.shared.b16 {%0,%1,%2,%3}, [%4];"
        : "=r"(r[0]), "=r"(r[1]), "=r"(r[2]), "=r"(r[3]) : "r"(addr));
}
__device__ __forceinline__ void mma_bf16(float* c, const uint32_t* a,
                                         uint32_t b0, uint32_t b1) {
    asm volatile(
        "mma.sync.aligned.m16n8k16.row.col.f32.bf16.bf16.f32 "
        "{%0,%1,%2,%3}, {%4,%5,%6,%7}, {%8,%9}, {%0,%1,%2,%3};"
        : "+f"(c[0]), "+f"(c[1]), "+f"(c[2]), "+f"(c[3])
        : "r"(a[0]), "r"(a[1]), "r"(a[2]), "r"(a[3]), "r"(b0), "r"(b1));
}
__device__ __forceinline__ uint32_t pack2(__nv_bfloat16 a, __nv_bfloat16 b) {
    union { __nv_bfloat162 v; uint32_t u; } c;
    c.v = __nv_bfloat162(a, b);
    return c.u;
}
__device__ __forceinline__ void split_store4(float4 v,
                                             __nv_bfloat16* hip,
                                             __nv_bfloat16* lop) {
    __nv_bfloat16 h0 = __float2bfloat16_rn(v.x);
    __nv_bfloat16 h1 = __float2bfloat16_rn(v.y);
    __nv_bfloat16 h2 = __float2bfloat16_rn(v.z);
    __nv_bfloat16 h3 = __float2bfloat16_rn(v.w);
    __nv_bfloat16 l0 = __float2bfloat16_rn(v.x - __bfloat162float(h0));
    __nv_bfloat16 l1 = __float2bfloat16_rn(v.y - __bfloat162float(h1));
    __nv_bfloat16 l2 = __float2bfloat16_rn(v.z - __bfloat162float(h2));
    __nv_bfloat16 l3 = __float2bfloat16_rn(v.w - __bfloat162float(h3));
    ((uint32_t*)hip)[0] = pack2(h0, h1);
    ((uint32_t*)hip)[1] = pack2(h2, h3);
    ((uint32_t*)lop)[0] = pack2(l0, l1);
    ((uint32_t*)lop)[1] = pack2(l2, l3);
}

// ---- MUFU-free activations (FMA/ALU pipes only) ----
__device__ __forceinline__ float fast_exp(float x) {
    // caller guarantees |x| <= 61; rel err ~1e-7
    const float L2E = 1.4426950408889634f;
    float t  = fmaf(x, L2E, 12582912.0f);            // round(x*log2e) in mantissa
    int   n  = __float_as_int(t) - 0x4B400000;
    float nf = t - 12582912.0f;
    float r  = fmaf(nf, -0.693359375f, x);           // Cody-Waite hi
    r = fmaf(nf, 2.12194440e-4f, r);                 // Cody-Waite lo
    float p = 1.9841270e-4f;                         // 1/5040
    p = fmaf(p, r, 1.3888889e-3f);                   // 1/720
    p = fmaf(p, r, 8.3333333e-3f);                   // 1/120
    p = fmaf(p, r, 4.1666667e-2f);                   // 1/24
    p = fmaf(p, r, 1.6666667e-1f);                   // 1/6
    p = fmaf(p, r, 0.5f);
    p = fmaf(p, r, 1.0f);
    p = fmaf(p, r, 1.0f);
    return __int_as_float(__float_as_int(p) + (n << 23));
}
__device__ __forceinline__ float fast_rcp(float d) {
    // d > 0; rel err ~1e-7 after 3 Newton steps
    float r = __int_as_float(0x7EF127EAu - __float_as_int(d));
    r = r * fmaf(-d, r, 2.0f);
    r = r * fmaf(-d, r, 2.0f);
    r = r * fmaf(-d, r, 2.0f);
    return r;
}
__device__ __forceinline__ float fsig(float x) {
    x = fminf(fmaxf(x, -30.0f), 30.0f);
    float e = fast_exp(-x);
    return fast_rcp(1.0f + e);
}
__device__ __forceinline__ float ftanh(float x) {
    return fmaf(2.0f, fsig(2.0f * x), -1.0f);
}

// ===========================================================================
// Kernel 1: x_proj = inputs @ Wx + b (unchanged — measured ~1.2 ms)
// ===========================================================================
#define XBM 128
#define XBN 128
#define XBK 32
#define KPA 40
#define NPB 136
#define A_TERM_ELEMS (XBM * KPA)
#define B_TERM_ELEMS (XBK * NPB)
#define STAGE_ELEMS  (2 * A_TERM_ELEMS + 2 * B_TERM_ELEMS)
#define XSMEM_BYTES  (2 * STAGE_ELEMS * 2)

__global__ __launch_bounds__(256) void xproj_mma_kernel(
    const float* __restrict__ A,
    const float* __restrict__ W,
    const float* __restrict__ bias)
{
    extern __shared__ __nv_bfloat16 xsm[];

    const int tid   = threadIdx.x;
    const int lane  = tid & 31;
    const int wid   = tid >> 5;
    const int warpM = wid & 3;
    const int warpN = wid >> 2;
    const int bM    = blockIdx.y;
    const int bN    = blockIdx.x;

    const int arow0 = tid >> 3;
    const int ac4   = tid & 7;
    const int bkr0  = tid >> 5;
    const int bn4   = tid & 31;

    const float* Ag = A + (size_t)bM * XBM * DIM;
    const float* Wg = W + (size_t)bN * XBN;

    float acc[2][8][4];
    #pragma unroll
    for (int mt = 0; mt < 2; mt++)
        #pragma unroll
        for (int j = 0; j < 8; j++)
            #pragma unroll
            for (int q = 0; q < 4; q++) acc[mt][j][q] = 0.f;

    const int a_row_l = (lane & 15);
    const int a_koff  = ((lane >> 4) << 3);
    const int b_krow  = (lane & 7) + ((lane >> 3) & 1) * 8;
    const int b_ncol  = ((lane >> 4) & 1) * 8;

    float4 aReg[4], bReg[4];

    #pragma unroll
    for (int i = 0; i < 4; i++) {
        aReg[i] = *(const float4*)(Ag + (size_t)(arow0 + 32 * i) * DIM + ac4 * 4);
        bReg[i] = *(const float4*)(Wg + (size_t)(bkr0 + 8 * i) * FOURH + bn4 * 4);
    }
    {
        __nv_bfloat16* Ahi = xsm;
        __nv_bfloat16* Alo = Ahi + A_TERM_ELEMS;
        __nv_bfloat16* Bhi = Alo + A_TERM_ELEMS;
        __nv_bfloat16* Blo = Bhi + B_TERM_ELEMS;
        #pragma unroll
        for (int i = 0; i < 4; i++) {
            int ar = arow0 + 32 * i;
            split_store4(aReg[i], &Ahi[ar * KPA + ac4 * 4], &Alo[ar * KPA + ac4 * 4]);
            int bk = bkr0 + 8 * i;
            split_store4(bReg[i], &Bhi[bk * NPB + bn4 * 4], &Blo[bk * NPB + bn4 * 4]);
        }
    }
    __syncthreads();

    const int NSTAGE = DIM / XBK;

    for (int s = 0; s < NSTAGE; s++) {
        if (s + 1 < NSTAGE) {
            int k0 = (s + 1) * XBK;
            #pragma unroll
            for (int i = 0; i < 4; i++) {
                aReg[i] = *(const float4*)(Ag + (size_t)(arow0 + 32 * i) * DIM + k0 + ac4 * 4);
                bReg[i] = *(const float4*)(Wg + (size_t)(k0 + bkr0 + 8 * i) * FOURH + bn4 * 4);
            }
        }

        const __nv_bfloat16* st = xsm + (s & 1) * STAGE_ELEMS;
        uint32_t sAhi = smem_u32(st);
        uint32_t sAlo = sAhi + A_TERM_ELEMS * 2;
        uint32_t sBhi = sAlo + A_TERM_ELEMS * 2;
        uint32_t sBlo = sBhi + B_TERM_ELEMS * 2;

        #pragma unroll
        for (int ks = 0; ks < 2; ks++) {
            const int kk0 = ks * 16;
            uint32_t aHi[2][4], aLo[2][4];
            #pragma unroll
            for (int mt = 0; mt < 2; mt++) {
                uint32_t off =
                    (uint32_t)((warpM * 32 + mt * 16 + a_row_l) * KPA + kk0 + a_koff) * 2;
                ldsm_x4(aHi[mt], sAhi + off);
                ldsm_x4(aLo[mt], sAlo + off);
            }
            uint32_t bHi[4][4], bLo[4][4];
            #pragma unroll
            for (int nt = 0; nt < 4; nt++) {
                uint32_t off =
                    (uint32_t)((kk0 + b_krow) * NPB + warpN * 64 + nt * 16 + b_ncol) * 2;
                ldsm_x4_t(bHi[nt], sBhi + off);
                ldsm_x4_t(bLo[nt], sBlo + off);
            }
            #pragma unroll
            for (int mt = 0; mt < 2; mt++) {
                #pragma unroll
                for (int j = 0; j < 8; j++) {
                    uint32_t bh0 = bHi[j >> 1][(j & 1) * 2];
                    uint32_t bh1 = bHi[j >> 1][(j & 1) * 2 + 1];
                    uint32_t bl0 = bLo[j >> 1][(j & 1) * 2];
                    uint32_t bl1 = bLo[j >> 1][(j & 1) * 2 + 1];
                    mma_bf16(acc[mt][j], aHi[mt], bh0, bh1);
                    mma_bf16(acc[mt][j], aHi[mt], bl0, bl1);
                    mma_bf16(acc[mt][j], aLo[mt], bh0, bh1);
                }
            }
        }

        if (s + 1 < NSTAGE) {
            __nv_bfloat16* dst = xsm + ((s + 1) & 1) * STAGE_ELEMS;
            __nv_bfloat16* Ahi = dst;
            __nv_bfloat16* Alo = Ahi + A_TERM_ELEMS;
            __nv_bfloat16* Bhi = Alo + A_TERM_ELEMS;
            __nv_bfloat16* Blo = Bhi + B_TERM_ELEMS;
            #pragma unroll
            for (int i = 0; i < 4; i++) {
                int ar = arow0 + 32 * i;
                split_store4(aReg[i], &Ahi[ar * KPA + ac4 * 4], &Alo[ar * KPA + ac4 * 4]);
                int bk = bkr0 + 8 * i;
                split_store4(bReg[i], &Bhi[bk * NPB + bn4 * 4], &Blo[bk * NPB + bn4 * 4]);
            }
        }
        __syncthreads();
    }

    const int g  = lane >> 2;
    const int t2 = (lane & 3) * 2;
    #pragma unroll
    for (int mt = 0; mt < 2; mt++) {
        int row = bM * XBM + warpM * 32 + mt * 16 + g;
        #pragma unroll
        for (int j = 0; j < 8; j++) {
            int col = bN * XBN + warpN * 64 + j * 8 + t2;
            float b0 = bias[col], b1 = bias[col + 1];
            float2 o0 = make_float2(acc[mt][j][0] + b0, acc[mt][j][1] + b1);
            float2 o1 = make_float2(acc[mt][j][2] + b0, acc[mt][j][3] + b1);
            *(float2*)&g_xproj[(size_t)row * FOURH + col] = o0;
            *(float2*)&g_xproj[(size_t)(row + 8) * FOURH + col] = o1;
        }
    }
}

// ===========================================================================
// Kernel 2: recurrent kernel — tensor-core matvec + vector DSMEM bcast +
// MUFU-free gating.
// ===========================================================================
#define CLUSTER 8
#define NB      16
#define LC      128
#define RTHREADS 256

#define HSTRIDE 264
#define WSTRIDE 136
#define ZSTRIDE 132

#define SMB_WHHI 0
#define SMB_WHLO (SMB_WHHI + 256 * WSTRIDE * 2)
#define SMB_HB   (SMB_WHLO + 256 * WSTRIDE * 2)
#define HB_ARR_BYTES (NB * HSTRIDE * 2)
#define HB_BUF_BYTES (2 * HB_ARR_BYTES)
#define SMB_Z    (SMB_HB + 2 * HB_BUF_BYTES)
#define SMB_C    (SMB_Z + NB * ZSTRIDE * 4)
#define SMB_WO   (SMB_C + NB * 32 * 4)
#define SMB_BO   (SMB_WO + 5 * 256 * 4)
#define RSMEM_BYTES (SMB_BO + 32)

__device__ __forceinline__ void st_cluster_v4(uint32_t saddr, int rank,
                                              uint32_t a, uint32_t b,
                                              uint32_t c, uint32_t d) {
    asm volatile(
        "{ .reg .b32 ra; mapa.shared::cluster.u32 ra, %0, %1;"
        "  st.shared::cluster.v4.b32 [ra], {%2,%3,%4,%5}; }"
        :: "r"(saddr), "r"(rank), "r"(a), "r"(b), "r"(c), "r"(d) : "memory");
}

__global__ void __cluster_dims__(CLUSTER, 1, 1) __launch_bounds__(RTHREADS, 1)
lstm_rec_kernel(const int*   __restrict__ epi,
                const float* __restrict__ carry_c,
                const float* __restrict__ carry_h,
                const float* __restrict__ Wh,
                const float* __restrict__ Wa,
                const float* __restrict__ ba,
                const float* __restrict__ Wv,
                const float* __restrict__ bv,
                float*       __restrict__ out)
{
    extern __shared__ char smraw[];
    __nv_bfloat16* WhHi = (__nv_bfloat16*)(smraw + SMB_WHHI);
    __nv_bfloat16* WhLo = (__nv_bfloat16*)(smraw + SMB_WHLO);
    float* z_s  = (float*)(smraw + SMB_Z);
    float* c_s  = (float*)(smraw + SMB_C);
    float* Wo_s = (float*)(smraw + SMB_WO);
    float* bo_s = (float*)(smraw + SMB_BO);

    const int tid  = threadIdx.x;
    const int lane = tid & 31;
    const int wid  = tid >> 5;
    uint32_t rank;
    asm("mov.u32 %0, %%cluster_ctarank;" : "=r"(rank));
    const int cl = blockIdx.x / CLUSTER;
    const int b0 = cl * NB;

    for (int idx = tid; idx < 256 * LC; idx += RTHREADS) {
        int k = idx >> 7;
        int c = idx & 127;
        int gcol = ((c >> 5) << 8) + ((int)rank << 5) + (c & 31);
        float w = Wh[k * FOURH + gcol];
        __nv_bfloat16 hi = __float2bfloat16_rn(w);
        __nv_bfloat16 lo = __float2bfloat16_rn(w - __bfloat162float(hi));
        WhHi[k * WSTRIDE + c] = hi;
        WhLo[k * WSTRIDE + c] = lo;
    }
    for (int idx = tid; idx < NB * HID; idx += RTHREADS) {
        int b = idx >> 8;
        int k = idx & 255;
        float v = carry_h[(size_t)(b0 + b) * HID + k];
        __nv_bfloat16 hi = __float2bfloat16_rn(v);
        __nv_bfloat16 lo = __float2bfloat16_rn(v - __bfloat162float(hi));
        __nv_bfloat16* hHi = (__nv_bfloat16*)(smraw + SMB_HB + 1 * HB_BUF_BYTES);
        __nv_bfloat16* hLo = hHi + NB * HSTRIDE;
        hHi[b * HSTRIDE + k] = hi;
        hLo[b * HSTRIDE + k] = lo;
    }
    for (int idx = tid; idx < NB * 32; idx += RTHREADS) {
        int b = idx >> 5;
        int j = idx & 31;
        c_s[idx] = carry_c[(size_t)(b0 + b) * HID + (int)rank * 32 + j];
    }
    #pragma unroll
    for (int q = 0; q < 5; q++) {
        int col = (int)rank + 8 * q;
        if (col <= 32) {
            for (int k = tid; k < HID; k += RTHREADS)
                Wo_s[q * 256 + k] = (col < 32) ? Wa[k * NACT + col] : Wv[k];
            if (tid == 0) bo_s[q] = (col < 32) ? ba[col] : bv[0];
        }
    }
    __syncthreads();

    const int a_row_l = (lane & 15);
    const int a_koff  = ((lane >> 4) << 3);
    const int b_krow  = (lane & 7) + ((lane >> 3) & 1) * 8;
    const int b_ncol  = ((lane >> 4) & 1) * 8;

    const uint32_t sWhHi = smem_u32(WhHi);
    const uint32_t sWhLo = smem_u32(WhLo);

    int ep_reg = epi[0 * BATCH + b0 + (tid >> 4)];

    for (int t = 0; t < T_STEPS; t++) {
        const int p_out = t & 1;
        const int p_in  = p_out ^ 1;
        __nv_bfloat16* hinHi  = (__nv_bfloat16*)(smraw + SMB_HB + p_in * HB_BUF_BYTES);
        __nv_bfloat16* hinLo  = hinHi + NB * HSTRIDE;
        __nv_bfloat16* houtHi = (__nv_bfloat16*)(smraw + SMB_HB + p_out * HB_BUF_BYTES);
        __nv_bfloat16* houtLo = houtHi + NB * HSTRIDE;

        const size_t xbase = (size_t)t * BATCH * FOURH;
        float xi[2], xf[2], xg[2], xo[2];
        #pragma unroll
        for (int pp = 0; pp < 2; pp++) {
            int pr = tid + pp * 256;
            int b = pr >> 5, j = pr & 31;
            size_t base = xbase + (size_t)(b0 + b) * FOURH + (int)rank * 32 + j;
            xi[pp] = g_xproj[base];
            xf[pp] = g_xproj[base + 256];
            xg[pp] = g_xproj[base + 512];
            xo[pp] = g_xproj[base + 768];
        }

        {
            int b  = tid >> 4;
            int ch = tid & 15;
            if (ep_reg) {
                uint4 z4 = {0u, 0u, 0u, 0u};
                *(uint4*)&hinHi[b * HSTRIDE + ch * 16]     = z4;
                *(uint4*)&hinHi[b * HSTRIDE + ch * 16 + 8] = z4;
                *(uint4*)&hinLo[b * HSTRIDE + ch * 16]     = z4;
                *(uint4*)&hinLo[b * HSTRIDE + ch * 16 + 8] = z4;
                if (ch < 2) {
                    float4 zf = {0.f, 0.f, 0.f, 0.f};
                    #pragma unroll
                    for (int u = 0; u < 4; u++)
                        *(float4*)&c_s[b * 32 + ch * 16 + u * 4] = zf;
                }
            }
        }
        __syncthreads();

        // -- z = h @ Wh_slice via mma: M=16, N=128 (16/warp), K=256 --
        {
            const uint32_t sHinHi = smem_u32(hinHi);
            const uint32_t sHinLo = smem_u32(hinLo);
            float acc[2][4];
            #pragma unroll
            for (int t2 = 0; t2 < 2; t2++)
                #pragma unroll
                for (int q = 0; q < 4; q++) acc[t2][q] = 0.f;

            #pragma unroll 8
            for (int ks = 0; ks < 16; ks++) {
                const int kk0 = ks * 16;
                uint32_t aoff = (uint32_t)(a_row_l * HSTRIDE + kk0 + a_koff) * 2;
                uint32_t aHi[4], aLo[4];
                ldsm_x4(aHi, sHinHi + aoff);
                ldsm_x4(aLo, sHinLo + aoff);
                uint32_t boff =
                    (uint32_t)((kk0 + b_krow) * WSTRIDE + wid * 16 + b_ncol) * 2;
                uint32_t bHi[4], bLo[4];
                ldsm_x4_t(bHi, sWhHi + boff);
                ldsm_x4_t(bLo, sWhLo + boff);
                #pragma unroll
                for (int t2 = 0; t2 < 2; t2++) {
                    mma_bf16(acc[t2], aHi, bHi[t2 * 2], bHi[t2 * 2 + 1]);
                    mma_bf16(acc[t2], aHi, bLo[t2 * 2], bLo[t2 * 2 + 1]);
                    mma_bf16(acc[t2], aLo, bHi[t2 * 2], bHi[t2 * 2 + 1]);
                }
            }
            int r0 = lane >> 2;
            int cb = wid * 16 + 2 * (lane & 3);
            #pragma unroll
            for (int t2 = 0; t2 < 2; t2++) {
                int col = cb + 8 * t2;
                *(float2*)&z_s[r0 * ZSTRIDE + col] =
                    make_float2(acc[t2][0], acc[t2][1]);
                *(float2*)&z_s[(r0 + 8) * ZSTRIDE + col] =
                    make_float2(acc[t2][2], acc[t2][3]);
            }
        }

        if (t + 1 < T_STEPS)
            ep_reg = epi[(t + 1) * BATCH + b0 + (tid >> 4)];

        __syncthreads();

        // -- gating (MUFU-free activations) --
        #pragma unroll
        for (int pp = 0; pp < 2; pp++) {
            int pr = tid + pp * 256;
            int b = pr >> 5, j = pr & 31;
            float iz = z_s[b * ZSTRIDE + j]      + xi[pp];
            float fz = z_s[b * ZSTRIDE + 32 + j] + xf[pp];
            float gz = z_s[b * ZSTRIDE + 64 + j] + xg[pp];
            float oz = z_s[b * ZSTRIDE + 96 + j] + xo[pp];
            float c_old = c_s[b * 32 + j];
            float nc = fsig(fz) * c_old + fsig(iz) * ftanh(gz);
            float nh = fsig(oz) * ftanh(nc);
            c_s[b * 32 + j] = nc;
            __nv_bfloat16 hi = __float2bfloat16_rn(nh);
            __nv_bfloat16 lo = __float2bfloat16_rn(nh - __bfloat162float(hi));
            int hoff = b * HSTRIDE + (int)rank * 32 + j;
            houtHi[hoff] = hi;
            houtLo[hoff] = lo;
        }
        __syncthreads();

        // -- vectorized DSMEM broadcast of local slice --
        if (tid < 128) {
            int arr = tid >> 6;
            int row = (tid >> 2) & 15;
            int seg = tid & 3;
            __nv_bfloat16* base = arr ? houtLo : houtHi;
            uint32_t saddr = smem_u32(base) +
                             (uint32_t)(row * HSTRIDE + (int)rank * 32) * 2 + seg * 16;
            uint4 v = *(const uint4*)((const char*)base +
                         (size_t)(row * HSTRIDE + (int)rank * 32) * 2 + seg * 16);
            #pragma unroll
            for (int rr = 0; rr < CLUSTER; rr++)
                if (rr != (int)rank)
                    st_cluster_v4(saddr, rr, v.x, v.y, v.z, v.w);
        }

        asm volatile("barrier.cluster.arrive.aligned;" ::: "memory");
        asm volatile("barrier.cluster.wait.aligned;"   ::: "memory");

        // -- output head: 8 independent reduce chains, fully unrolled --
        {
            float sacc[8];
            #pragma unroll
            for (int u = 0; u < 8; u++) {
                int task = wid + 8 * u;
                int q = task >> 4;
                int b = task & 15;
                const __nv_bfloat16* hHr = &houtHi[b * HSTRIDE];
                const __nv_bfloat16* hLr = &houtLo[b * HSTRIDE];
                const float* wcol = &Wo_s[q * 256];
                float s = 0.f;
                #pragma unroll
                for (int uu = 0; uu < 8; uu++) {
                    int k = lane + 32 * uu;
                    float hv = __bfloat162float(hHr[k]) + __bfloat162float(hLr[k]);
                    s = fmaf(hv, wcol[k], s);
                }
                sacc[u] = s;
            }
            #pragma unroll
            for (int u = 0; u < 8; u++) {
                float s = sacc[u];
                #pragma unroll
                for (int off = 16; off; off >>= 1)
                    s += __shfl_xor_sync(0xFFFFFFFFu, s, off);
                if (lane == 0) {
                    int task = wid + 8 * u;
                    int q = task >> 4;
                    int b = task & 15;
                    int col = (int)rank + 8 * q;
                    out[((size_t)t * BATCH + b0 + b) * OUTC + col] = s + bo_s[q];
                }
            }
            if (rank == 0) {
                #pragma unroll
                for (int u = 0; u < 2; u++) {
                    int b = wid + 8 * u;
                    const __nv_bfloat16* hHr = &houtHi[b * HSTRIDE];
                    const __nv_bfloat16* hLr = &houtLo[b * HSTRIDE];
                    const float* wcol = &Wo_s[4 * 256];
                    float s = 0.f;
                    #pragma unroll
                    for (int uu = 0; uu < 8; uu++) {
                        int k = lane + 32 * uu;
                        float hv = __bfloat162float(hHr[k]) + __bfloat162float(hLr[k]);
                        s = fmaf(hv, wcol[k], s);
                    }
                    #pragma unroll
                    for (int off = 16; off; off >>= 1)
                        s += __shfl_xor_sync(0xFFFFFFFFu, s, off);
                    if (lane == 0)
                        out[((size_t)t * BATCH + b0 + b) * OUTC + 32] = s + bo_s[4];
                }
            }
        }
        __syncthreads();
    }
}

// ---------------------------------------------------------------------------
extern "C" void kernel_launch(void* const* d_in, const int* in_sizes, int n_in,
                              void* d_out, int out_size) {
    const float* inputs  = (const float*)d_in[0];
    const int*   epi     = (const int*)  d_in[1];
    const float* carry_c = (const float*)d_in[2];
    const float* carry_h = (const float*)d_in[3];
    const float* Wx      = (const float*)d_in[4];
    const float* Wh      = (const float*)d_in[5];
    const float* bias    = (const float*)d_in[6];
    const float* Wa      = (const float*)d_in[7];
    const float* ba      = (const float*)d_in[8];
    const float* Wv      = (const float*)d_in[9];
    const float* bv      = (const float*)d_in[10];
    float* out = (float*)d_out;

    cudaFuncSetAttribute(xproj_mma_kernel,
                         cudaFuncAttributeMaxDynamicSharedMemorySize, XSMEM_BYTES);
    cudaFuncSetAttribute(lstm_rec_kernel,
                         cudaFuncAttributeMaxDynamicSharedMemorySize, RSMEM_BYTES);

    dim3 g1(FOURH / XBN, (T_STEPS * BATCH) / XBM);
    xproj_mma_kernel<<<g1, 256, XSMEM_BYTES>>>(inputs, Wx, bias);

    lstm_rec_kernel<<<(BATCH / NB) * CLUSTER, RTHREADS, RSMEM_BYTES>>>(
        epi, carry_c, carry_h, Wh, Wa, ba, Wv, bv, out);
}